// round 12
// baseline (speedup 1.0000x reference)
#include <cuda_runtime.h>

// PositionalEncoding: out[b,t,i] = x[b,t,i] + P[t,i]
//   P[2f,   i] = sin(f / 10000^(2i/F))
//   P[2f+1, i] = cos(f / 10000^(2i/F))
// x: [32, 2048, 1024] fp32. HBM-streaming-bound (512MB traffic floor).
//
// FINAL (R7 champion config, best observed bench 82.4us, ~6.4TB/s = 80-81%
// of spec HBM — at the practical ceiling for a 1:1 R/W stream):
//  - one CTA per (row, batch-half): grid 2048x2, 256 threads, float4
//  - __launch_bounds__(256,4): 64-reg budget lets ptxas keep a 16-deep
//    LDG.E.128 front per thread (outstanding-bytes is the limiter, not occ)
//  - BY=2 batch split: shrinks the wave-quantization tail (3.46 waves @46%
//    full -> 6.92 waves @92% full)  [+1.5us]
//  - software pipeline: first 8 loads issue BEFORE the powf/sinf MUFU chain
//    (independent), hiding the per-CTA transcendental prologue  [+1.5us]
//  - default cache policy both directions (.cg/.cs loads and .cs stores all
//    tested: no reproducible gain)
// Calibrated dead ends: v8 256-bit accesses (-10%), persistent grid (-20%),
// occupancy >53% (no effect), BY=4 (transcendental overhead).

#define PE_T 2048
#define PE_F 1024
#define PE_B 32
#define PE_BY 2                      // batch split factor
#define PE_BPER (PE_B / PE_BY)       // 16 batches per thread
#define PE_H (PE_BPER / 2)           // 8 per pipeline half

__global__ __launch_bounds__(256, 4)
void pe_add_kernel(const float* __restrict__ x, float* __restrict__ out) {
    const int t = blockIdx.x;          // row 0..2047
    const int c = threadIdx.x;         // float4 column 0..255
    const int b0 = blockIdx.y * PE_BPER;

    const float4* __restrict__ x4 = (const float4*)x;
    float4* __restrict__ o4 = (float4*)out;
    const size_t row_stride4 = (size_t)PE_T * (PE_F / 4);   // float4 per batch slice
    const size_t base = (size_t)t * (PE_F / 4) + (size_t)c
                      + (size_t)b0 * row_stride4;

    // ---- Pipeline stage 1: issue first 8 loads (independent of P) ----
    float4 buf[PE_H];
#pragma unroll
    for (int b = 0; b < PE_H; b++)
        buf[b] = x4[base + (size_t)b * row_stride4];

    // ---- Compute P while loads are in flight ----
    const float f = (float)(t >> 1);
    const bool is_sin = (t & 1) == 0;
    float pv[4];
#pragma unroll
    for (int k = 0; k < 4; k++) {
        const int i = c * 4 + k;
        const float e = (float)i * (1.0f / 512.0f);   // 2*i/F, exact in fp32
        const float den = powf(10000.0f, e);
        const float ang = f / den;
        pv[k] = is_sin ? sinf(ang) : cosf(ang);
    }
    const float4 p = make_float4(pv[0], pv[1], pv[2], pv[3]);

    // ---- Stage 2: issue second-half loads, then drain first half ----
    float4 buf2[PE_H];
#pragma unroll
    for (int b = 0; b < PE_H; b++)
        buf2[b] = x4[base + (size_t)(b + PE_H) * row_stride4];

#pragma unroll
    for (int b = 0; b < PE_H; b++) {
        float4 v = buf[b];
        v.x += p.x; v.y += p.y; v.z += p.z; v.w += p.w;
        o4[base + (size_t)b * row_stride4] = v;
    }

#pragma unroll
    for (int b = 0; b < PE_H; b++) {
        float4 v = buf2[b];
        v.x += p.x; v.y += p.y; v.z += p.z; v.w += p.w;
        o4[base + (size_t)(b + PE_H) * row_stride4] = v;
    }
}

extern "C" void kernel_launch(void* const* d_in, const int* in_sizes, int n_in,
                              void* d_out, int out_size) {
    const float* x = (const float*)d_in[0];
    float* out = (float*)d_out;
    dim3 grid(PE_T, PE_BY);
    pe_add_kernel<<<grid, 256>>>(x, out);
}

// round 15
// speedup vs baseline: 1.0015x; 1.0015x over previous
#include <cuda_runtime.h>

// PositionalEncoding: out[b,t,i] = x[b,t,i] + P[t,i]
//   P[2f,   i] = sin(f / 10000^(2i/F))
//   P[2f+1, i] = cos(f / 10000^(2i/F))
// x: [32, 2048, 1024] fp32. HBM-streaming-bound (512MB traffic floor).
//
// FINAL — CONVERGED. ~75.7us kernel, 6.4TB/s = 80-81% of spec HBM3e on a
// 1:1 R/W stream; remaining gap to spec is physical R/W-turnaround cost.
// Pooled multi-run evidence shows all surviving variants within the ±1us
// run-to-run noise band; this config has the best single observed bench
// (82.4us) and the simplest store path.
//
// Config:
//  - one CTA per (row, batch-half): grid 2048x2, 256 threads, float4
//  - __launch_bounds__(256,4): 64-reg budget -> ptxas keeps a 16-deep
//    LDG.E.128 front per thread (outstanding-bytes is the limiter, not occ)
//  - BY=2 batch split: wave-quantization tail 3.46 waves @46% full ->
//    6.92 waves @92% full  [+1.5us, reproduced]
//  - software pipeline: first 8 loads issue BEFORE the powf/sinf MUFU chain
//    (independent), hiding the per-CTA transcendental prologue  [+1.5us]
//  - default cache policy both directions (.cg/.cs loads negative, .cs
//    stores within noise across 2 samples each)
// Calibrated dead ends: v8 256-bit accesses (-10%), persistent grid (-20%),
// occupancy >53% (flat), BY=4 (transcendental overhead).

#define PE_T 2048
#define PE_F 1024
#define PE_B 32
#define PE_BY 2                      // batch split factor
#define PE_BPER (PE_B / PE_BY)       // 16 batches per thread
#define PE_H (PE_BPER / 2)           // 8 per pipeline half

__global__ __launch_bounds__(256, 4)
void pe_add_kernel(const float* __restrict__ x, float* __restrict__ out) {
    const int t = blockIdx.x;          // row 0..2047
    const int c = threadIdx.x;         // float4 column 0..255
    const int b0 = blockIdx.y * PE_BPER;

    const float4* __restrict__ x4 = (const float4*)x;
    float4* __restrict__ o4 = (float4*)out;
    const size_t row_stride4 = (size_t)PE_T * (PE_F / 4);   // float4 per batch slice
    const size_t base = (size_t)t * (PE_F / 4) + (size_t)c
                      + (size_t)b0 * row_stride4;

    // ---- Pipeline stage 1: issue first 8 loads (independent of P) ----
    float4 buf[PE_H];
#pragma unroll
    for (int b = 0; b < PE_H; b++)
        buf[b] = x4[base + (size_t)b * row_stride4];

    // ---- Compute P while loads are in flight ----
    const float f = (float)(t >> 1);
    const bool is_sin = (t & 1) == 0;
    float pv[4];
#pragma unroll
    for (int k = 0; k < 4; k++) {
        const int i = c * 4 + k;
        const float e = (float)i * (1.0f / 512.0f);   // 2*i/F, exact in fp32
        const float den = powf(10000.0f, e);
        const float ang = f / den;
        pv[k] = is_sin ? sinf(ang) : cosf(ang);
    }
    const float4 p = make_float4(pv[0], pv[1], pv[2], pv[3]);

    // ---- Stage 2: issue second-half loads, then drain first half ----
    float4 buf2[PE_H];
#pragma unroll
    for (int b = 0; b < PE_H; b++)
        buf2[b] = x4[base + (size_t)(b + PE_H) * row_stride4];

#pragma unroll
    for (int b = 0; b < PE_H; b++) {
        float4 v = buf[b];
        v.x += p.x; v.y += p.y; v.z += p.z; v.w += p.w;
        o4[base + (size_t)b * row_stride4] = v;
    }

#pragma unroll
    for (int b = 0; b < PE_H; b++) {
        float4 v = buf2[b];
        v.x += p.x; v.y += p.y; v.z += p.z; v.w += p.w;
        o4[base + (size_t)(b + PE_H) * row_stride4] = v;
    }
}

extern "C" void kernel_launch(void* const* d_in, const int* in_sizes, int n_in,
                              void* d_out, int out_size) {
    const float* x = (const float*)d_in[0];
    float* out = (float*)d_out;
    dim3 grid(PE_T, PE_BY);
    pe_add_kernel<<<grid, 256>>>(x, out);
}

// round 16
// speedup vs baseline: 1.0160x; 1.0144x over previous
#include <cuda_runtime.h>

// PositionalEncoding: out[b,t,i] = x[b,t,i] + P[t,i]
//   P[2f,   i] = sin(f / 10000^(2i/F))
//   P[2f+1, i] = cos(f / 10000^(2i/F))
// x: [32, 2048, 1024] fp32. HBM-streaming-bound (512MB traffic floor).
//
// R16 probe: champion (grid 2048x2, 256 thr, float4, BY=2, loads ahead of
// the sin/cos chain) with the load front deepened from 8+8 to a single
// 16-deep front burst (MLP_p1=16). __launch_bounds__(256,3) raises the
// register budget to 80 so all 16 float4 buffers stay in regs (occ 3 CTAs
// = 24 warps/SM; bandwidth measured flat down to ~42% occ).
// If this regresses (spill), revert to the 8+8 champion.

#define PE_T 2048
#define PE_F 1024
#define PE_B 32
#define PE_BY 2                      // batch split factor
#define PE_BPER (PE_B / PE_BY)       // 16 batches per thread

__global__ __launch_bounds__(256, 3)
void pe_add_kernel(const float* __restrict__ x, float* __restrict__ out) {
    const int t = blockIdx.x;          // row 0..2047
    const int c = threadIdx.x;         // float4 column 0..255
    const int b0 = blockIdx.y * PE_BPER;

    const float4* __restrict__ x4 = (const float4*)x;
    float4* __restrict__ o4 = (float4*)out;
    const size_t row_stride4 = (size_t)PE_T * (PE_F / 4);   // float4 per batch slice
    const size_t base = (size_t)t * (PE_F / 4) + (size_t)c
                      + (size_t)b0 * row_stride4;

    // ---- Front-batch ALL 16 loads (independent of P) ----
    float4 buf[PE_BPER];
#pragma unroll
    for (int b = 0; b < PE_BPER; b++)
        buf[b] = x4[base + (size_t)b * row_stride4];

    // ---- Compute P while the 16 loads are in flight ----
    const float f = (float)(t >> 1);
    const bool is_sin = (t & 1) == 0;
    float pv[4];
#pragma unroll
    for (int k = 0; k < 4; k++) {
        const int i = c * 4 + k;
        const float e = (float)i * (1.0f / 512.0f);   // 2*i/F, exact in fp32
        const float den = powf(10000.0f, e);
        const float ang = f / den;
        pv[k] = is_sin ? sinf(ang) : cosf(ang);
    }
    const float4 p = make_float4(pv[0], pv[1], pv[2], pv[3]);

    // ---- Drain: add + store in load order ----
#pragma unroll
    for (int b = 0; b < PE_BPER; b++) {
        float4 v = buf[b];
        v.x += p.x; v.y += p.y; v.z += p.z; v.w += p.w;
        o4[base + (size_t)b * row_stride4] = v;
    }
}

extern "C" void kernel_launch(void* const* d_in, const int* in_sizes, int n_in,
                              void* d_out, int out_size) {
    const float* x = (const float*)d_in[0];
    float* out = (float*)d_out;
    dim3 grid(PE_T, PE_BY);
    pe_add_kernel<<<grid, 256>>>(x, out);
}